// round 4
// baseline (speedup 1.0000x reference)
#include <cuda_runtime.h>

// loss = sum_{i,j} (s_i - b_j)^2  with s = A @ x, A:[5000,20], b:[5000], x:[20]
//      = N*sum(s^2) - 2*sum(s)*sum(b) + N*sum(b^2)

#define N_ROWS 5000
#define N_FEAT 20
#define TPB    256
#define NBLK   ((N_ROWS + TPB - 1) / TPB)   // 20 blocks

// Per-block partials: [ss, ss2, bs, bs2]. Written fresh every launch (no
// reset needed, no atomics) -> deterministic under graph replay.
__device__ double g_partial[NBLK][4];

__inline__ __device__ double warp_sum(double v) {
    #pragma unroll
    for (int o = 16; o > 0; o >>= 1)
        v += __shfl_down_sync(0xffffffffu, v, o);
    return v;
}

__global__ void ls_partial_kernel(const float* __restrict__ A,
                                  const float* __restrict__ b,
                                  const float* __restrict__ x) {
    __shared__ float xs[N_FEAT];
    if (threadIdx.x < N_FEAT) xs[threadIdx.x] = x[threadIdx.x];
    __syncthreads();

    const int i = blockIdx.x * TPB + threadIdx.x;

    double ss = 0.0, ss2 = 0.0, bs = 0.0, bs2 = 0.0;
    if (i < N_ROWS) {
        // Row i of A: 20 floats = 80 bytes, 16B-aligned -> 5 float4 loads.
        const float4* row = reinterpret_cast<const float4*>(A + i * N_FEAT);
        float acc = 0.0f;
        #pragma unroll
        for (int k = 0; k < 5; k++) {
            float4 v = row[k];
            acc += v.x * xs[4 * k + 0];
            acc += v.y * xs[4 * k + 1];
            acc += v.z * xs[4 * k + 2];
            acc += v.w * xs[4 * k + 3];
        }
        float bv = b[i];
        ss  = (double)acc;
        ss2 = (double)acc * (double)acc;
        bs  = (double)bv;
        bs2 = (double)bv * (double)bv;
    }

    // Block reduction: warp shuffle, then cross-warp via shared.
    ss  = warp_sum(ss);
    ss2 = warp_sum(ss2);
    bs  = warp_sum(bs);
    bs2 = warp_sum(bs2);

    __shared__ double sm[4][TPB / 32];
    const int lane = threadIdx.x & 31;
    const int wid  = threadIdx.x >> 5;
    if (lane == 0) {
        sm[0][wid] = ss;
        sm[1][wid] = ss2;
        sm[2][wid] = bs;
        sm[3][wid] = bs2;
    }
    __syncthreads();

    if (wid == 0) {
        const int nw = TPB / 32;
        double v0 = (lane < nw) ? sm[0][lane] : 0.0;
        double v1 = (lane < nw) ? sm[1][lane] : 0.0;
        double v2 = (lane < nw) ? sm[2][lane] : 0.0;
        double v3 = (lane < nw) ? sm[3][lane] : 0.0;
        v0 = warp_sum(v0);
        v1 = warp_sum(v1);
        v2 = warp_sum(v2);
        v3 = warp_sum(v3);
        if (lane == 0) {
            g_partial[blockIdx.x][0] = v0;
            g_partial[blockIdx.x][1] = v1;
            g_partial[blockIdx.x][2] = v2;
            g_partial[blockIdx.x][3] = v3;
        }
    }
}

__global__ void ls_finalize_kernel(float* __restrict__ out) {
    const int lane = threadIdx.x;  // launched with 32 threads, NBLK <= 32
    double ss = 0.0, ss2 = 0.0, bs = 0.0, bs2 = 0.0;
    if (lane < NBLK) {
        ss  = g_partial[lane][0];
        ss2 = g_partial[lane][1];
        bs  = g_partial[lane][2];
        bs2 = g_partial[lane][3];
    }
    ss  = warp_sum(ss);
    ss2 = warp_sum(ss2);
    bs  = warp_sum(bs);
    bs2 = warp_sum(bs2);
    if (lane == 0) {
        const double N = (double)N_ROWS;
        out[0] = (float)(N * ss2 - 2.0 * ss * bs + N * bs2);
    }
}

extern "C" void kernel_launch(void* const* d_in, const int* in_sizes, int n_in,
                              void* d_out, int out_size) {
    const float* A = (const float*)d_in[0];  // [5000, 20]
    const float* b = (const float*)d_in[1];  // [5000]
    const float* x = (const float*)d_in[2];  // [20]
    float* out = (float*)d_out;              // scalar

    ls_partial_kernel<<<NBLK, TPB>>>(A, b, x);
    ls_finalize_kernel<<<1, 32>>>(out);
}